// round 1
// baseline (speedup 1.0000x reference)
#include <cuda_runtime.h>
#include <cuda_bf16.h>
#include <cstdint>

// Problem dims (fixed)
#define BB 2
#define SS 2048
#define DD 2048
#define HH 32
#define KVH 8
#define HD 64
#define NREP 4      // H / KVH
#define MTOT (BB*SS)  // 4096

// ---------------- scratch (static device allocations) ----------------
__device__ float g_q[(size_t)BB*SS*HH*HD];   // [b,s,h,d]  32MB
__device__ float g_k[(size_t)BB*SS*KVH*HD];  // [b,s,kvh,d] 8MB
__device__ float g_v[(size_t)BB*SS*KVH*HD];  // 8MB
__device__ float g_o[(size_t)BB*SS*HH*HD];   // 32MB

// ---------------- SGEMM: C[M,N] = A[M,K] @ B[N,K]^T (both row-major) ----------------
#define GBM 128
#define GBN 128
#define GBK 32

__global__ __launch_bounds__(256) void sgemm_nt(
    const float* __restrict__ A, const float* __restrict__ B,
    float* __restrict__ C, int M, int N, int K)
{
    __shared__ float As[GBK][GBM + 4];
    __shared__ float Bs[GBK][GBN + 4];

    const int tid = threadIdx.x;
    const int tx = tid & 15;          // 0..15 -> n micro
    const int ty = tid >> 4;          // 0..15 -> m micro
    const int m0 = blockIdx.y * GBM;
    const int n0 = blockIdx.x * GBN;

    const int lrow = tid >> 3;        // 0..31
    const int lk4  = (tid & 7) * 4;   // 0..28

    float acc[8][8];
    #pragma unroll
    for (int i = 0; i < 8; i++)
        #pragma unroll
        for (int j = 0; j < 8; j++) acc[i][j] = 0.0f;

    for (int k0 = 0; k0 < K; k0 += GBK) {
        #pragma unroll
        for (int r = 0; r < 4; r++) {
            int row = lrow + 32 * r;
            float4 va = *(const float4*)&A[(size_t)(m0 + row) * K + k0 + lk4];
            As[lk4 + 0][row] = va.x;
            As[lk4 + 1][row] = va.y;
            As[lk4 + 2][row] = va.z;
            As[lk4 + 3][row] = va.w;
            float4 vb = *(const float4*)&B[(size_t)(n0 + row) * K + k0 + lk4];
            Bs[lk4 + 0][row] = vb.x;
            Bs[lk4 + 1][row] = vb.y;
            Bs[lk4 + 2][row] = vb.z;
            Bs[lk4 + 3][row] = vb.w;
        }
        __syncthreads();

        #pragma unroll 8
        for (int kk = 0; kk < GBK; kk++) {
            float4 a0 = *(const float4*)&As[kk][ty * 8];
            float4 a1 = *(const float4*)&As[kk][ty * 8 + 4];
            float4 b0 = *(const float4*)&Bs[kk][tx * 8];
            float4 b1 = *(const float4*)&Bs[kk][tx * 8 + 4];
            float av[8] = {a0.x, a0.y, a0.z, a0.w, a1.x, a1.y, a1.z, a1.w};
            float bv[8] = {b0.x, b0.y, b0.z, b0.w, b1.x, b1.y, b1.z, b1.w};
            #pragma unroll
            for (int i = 0; i < 8; i++)
                #pragma unroll
                for (int j = 0; j < 8; j++)
                    acc[i][j] += av[i] * bv[j];
        }
        __syncthreads();
    }

    #pragma unroll
    for (int i = 0; i < 8; i++) {
        float4 v0 = make_float4(acc[i][0], acc[i][1], acc[i][2], acc[i][3]);
        float4 v1 = make_float4(acc[i][4], acc[i][5], acc[i][6], acc[i][7]);
        size_t base = (size_t)(m0 + ty * 8 + i) * N + n0 + tx * 8;
        *(float4*)&C[base]     = v0;
        *(float4*)&C[base + 4] = v1;
    }
}

// ---------------- RoPE (in-place, interleaved pairs) ----------------
__global__ void rope_kernel(float* __restrict__ buf,
                            const float* __restrict__ fc,
                            const float* __restrict__ fs,
                            int nh, int total)
{
    int idx = blockIdx.x * blockDim.x + threadIdx.x;
    if (idx >= total) return;
    int j = idx & 31;                  // freq index 0..31
    int t = idx >> 5;                  // row over [b,s,h]
    int s = (t / nh) % SS;
    float* p = buf + (size_t)t * HD + 2 * j;
    float2 v = *(float2*)p;
    float c = fc[s * 32 + j];
    float sn = fs[s * 32 + j];
    float2 r;
    r.x = v.x * c - v.y * sn;
    r.y = v.x * sn + v.y * c;
    *(float2*)p = r;
}

// ---------------- Flash attention (causal + pad mask), fp32 ----------------
// BQ=64 queries per CTA, BK=32 keys per tile, 256 threads (16x16).
// S micro-tile per thread: 4q x 2k.  O micro-tile: 4q x 4d.
#define NEG_BIG (-1e30f)

__global__ __launch_bounds__(256) void attn_kernel(
    const float* __restrict__ Qb, const float* __restrict__ Kb,
    const float* __restrict__ Vb, const int* __restrict__ amask,
    float* __restrict__ Ob)
{
    __shared__ float Qs[64][64];   // [d][q]  transposed
    __shared__ float Ks[64][34];   // [d][k]  transposed, padded
    __shared__ float Vs[32][64];   // [k][d]  natural
    __shared__ float Ps[32][65];   // [k][q]  transposed, padded
    __shared__ float Ms[32];       // additive mask per key

    const int tid = threadIdx.x;
    const int tx = tid & 15;
    const int ty = tid >> 4;
    const int qb = blockIdx.x;
    const int h  = blockIdx.y;
    const int b  = blockIdx.z;
    const int q0 = qb * 64;
    const int kvh = h >> 2;
    const float scale = 0.125f;   // 1/sqrt(64)

    // Load Q tile (scaled) transposed
    {
        int q  = tid >> 2;           // 0..63
        int dq = (tid & 3) * 4;      // 0,4,8,12
        const float* qp = Qb + (((size_t)b * SS + q0 + q) * HH + h) * HD;
        #pragma unroll
        for (int r = 0; r < 4; r++) {
            int d = dq + 16 * r;
            float4 v = *(const float4*)(qp + d);
            Qs[d + 0][q] = v.x * scale;
            Qs[d + 1][q] = v.y * scale;
            Qs[d + 2][q] = v.z * scale;
            Qs[d + 3][q] = v.w * scale;
        }
    }

    float m_i[4], l_i[4], o[4][4];
    #pragma unroll
    for (int i = 0; i < 4; i++) {
        m_i[i] = NEG_BIG;
        l_i[i] = 0.0f;
        #pragma unroll
        for (int j = 0; j < 4; j++) o[i][j] = 0.0f;
    }

    const int nkt = (q0 + 64) / 32;   // causal: tiles with k0 <= q0+63

    for (int kt = 0; kt < nkt; kt++) {
        const int k0 = kt * 32;
        // Load K (transposed) and V (natural)
        {
            int k  = tid >> 3;          // 0..31
            int dq = (tid & 7) * 4;     // 0..28
            const float* kp = Kb + (((size_t)b * SS + k0 + k) * KVH + kvh) * HD;
            const float* vp = Vb + (((size_t)b * SS + k0 + k) * KVH + kvh) * HD;
            float4 v1 = *(const float4*)(kp + dq);
            float4 v2 = *(const float4*)(kp + dq + 32);
            Ks[dq + 0][k] = v1.x; Ks[dq + 1][k] = v1.y;
            Ks[dq + 2][k] = v1.z; Ks[dq + 3][k] = v1.w;
            Ks[dq + 32][k] = v2.x; Ks[dq + 33][k] = v2.y;
            Ks[dq + 34][k] = v2.z; Ks[dq + 35][k] = v2.w;
            float4 w1 = *(const float4*)(vp + dq);
            float4 w2 = *(const float4*)(vp + dq + 32);
            *(float4*)&Vs[k][dq]      = w1;
            *(float4*)&Vs[k][dq + 32] = w2;
        }
        if (tid < 32) Ms[tid] = amask[b * SS + k0 + tid] ? 0.0f : NEG_BIG;
        __syncthreads();

        // S = Q K^T  (scaled Q already)
        float s[4][2];
        #pragma unroll
        for (int i = 0; i < 4; i++) { s[i][0] = 0.0f; s[i][1] = 0.0f; }
        #pragma unroll 16
        for (int d = 0; d < 64; d++) {
            float4 a = *(const float4*)&Qs[d][ty * 4];
            float2 bv = *(const float2*)&Ks[d][tx * 2];
            s[0][0] += a.x * bv.x; s[0][1] += a.x * bv.y;
            s[1][0] += a.y * bv.x; s[1][1] += a.y * bv.y;
            s[2][0] += a.z * bv.x; s[2][1] += a.z * bv.y;
            s[3][0] += a.w * bv.x; s[3][1] += a.w * bv.y;
        }

        // mask + online softmax per q row
        float msk0 = Ms[tx * 2 + 0];
        float msk1 = Ms[tx * 2 + 1];
        #pragma unroll
        for (int i = 0; i < 4; i++) {
            int qg = q0 + ty * 4 + i;
            float sv0 = s[i][0] + msk0;
            float sv1 = s[i][1] + msk1;
            if (k0 + tx * 2 + 0 > qg) sv0 = NEG_BIG;
            if (k0 + tx * 2 + 1 > qg) sv1 = NEG_BIG;
            float rmax = fmaxf(sv0, sv1);
            #pragma unroll
            for (int off = 8; off > 0; off >>= 1)
                rmax = fmaxf(rmax, __shfl_xor_sync(0xffffffffu, rmax, off));
            float mnew = fmaxf(m_i[i], rmax);
            float corr = __expf(m_i[i] - mnew);
            m_i[i] = mnew;
            float p0 = __expf(sv0 - mnew);
            float p1 = __expf(sv1 - mnew);
            float rsum = p0 + p1;
            #pragma unroll
            for (int off = 8; off > 0; off >>= 1)
                rsum += __shfl_xor_sync(0xffffffffu, rsum, off);
            l_i[i] = l_i[i] * corr + rsum;
            o[i][0] *= corr; o[i][1] *= corr; o[i][2] *= corr; o[i][3] *= corr;
            Ps[tx * 2 + 0][ty * 4 + i] = p0;
            Ps[tx * 2 + 1][ty * 4 + i] = p1;
        }
        __syncthreads();

        // O += P @ V
        #pragma unroll 8
        for (int k = 0; k < 32; k++) {
            float a0 = Ps[k][ty * 4 + 0];
            float a1 = Ps[k][ty * 4 + 1];
            float a2 = Ps[k][ty * 4 + 2];
            float a3 = Ps[k][ty * 4 + 3];
            float4 bv = *(const float4*)&Vs[k][tx * 4];
            o[0][0] += a0 * bv.x; o[0][1] += a0 * bv.y; o[0][2] += a0 * bv.z; o[0][3] += a0 * bv.w;
            o[1][0] += a1 * bv.x; o[1][1] += a1 * bv.y; o[1][2] += a1 * bv.z; o[1][3] += a1 * bv.w;
            o[2][0] += a2 * bv.x; o[2][1] += a2 * bv.y; o[2][2] += a2 * bv.z; o[2][3] += a2 * bv.w;
            o[3][0] += a3 * bv.x; o[3][1] += a3 * bv.y; o[3][2] += a3 * bv.z; o[3][3] += a3 * bv.w;
        }
        __syncthreads();
    }

    // epilogue: normalize and write [b,q,h,d]
    #pragma unroll
    for (int i = 0; i < 4; i++) {
        float inv = 1.0f / l_i[i];
        int q = q0 + ty * 4 + i;
        float4 v = make_float4(o[i][0] * inv, o[i][1] * inv, o[i][2] * inv, o[i][3] * inv);
        *(float4*)&Ob[(((size_t)b * SS + q) * HH + h) * HD + tx * 4] = v;
    }
}

// ---------------- launch ----------------
extern "C" void kernel_launch(void* const* d_in, const int* in_sizes, int n_in,
                              void* d_out, int out_size)
{
    const float* x  = (const float*)d_in[0];
    const float* fc = (const float*)d_in[1];
    const float* fs = (const float*)d_in[2];
    const float* wq = (const float*)d_in[3];
    const float* wk = (const float*)d_in[4];
    const float* wv = (const float*)d_in[5];
    const float* wo = (const float*)d_in[6];
    const int*   am = (const int*)d_in[7];
    float* out = (float*)d_out;

    float *pq, *pk, *pv, *po;
    cudaGetSymbolAddress((void**)&pq, g_q);
    cudaGetSymbolAddress((void**)&pk, g_k);
    cudaGetSymbolAddress((void**)&pv, g_v);
    cudaGetSymbolAddress((void**)&po, g_o);

    // QKV projections
    sgemm_nt<<<dim3(DD / GBN, MTOT / GBM), 256>>>(x, wq, pq, MTOT, DD, DD);
    sgemm_nt<<<dim3((KVH * HD) / GBN, MTOT / GBM), 256>>>(x, wk, pk, MTOT, KVH * HD, DD);
    sgemm_nt<<<dim3((KVH * HD) / GBN, MTOT / GBM), 256>>>(x, wv, pv, MTOT, KVH * HD, DD);

    // RoPE on Q and K
    {
        int totq = BB * SS * HH * 32;
        int totk = BB * SS * KVH * 32;
        rope_kernel<<<(totq + 255) / 256, 256>>>(pq, fc, fs, HH, totq);
        rope_kernel<<<(totk + 255) / 256, 256>>>(pk, fc, fs, KVH, totk);
    }

    // attention
    attn_kernel<<<dim3(SS / 64, HH, BB), 256>>>(pq, pk, pv, am, po);

    // output projection
    sgemm_nt<<<dim3(DD / GBN, MTOT / GBM), 256>>>(po, wo, out, MTOT, DD, DD);
}

// round 12
// speedup vs baseline: 1.6248x; 1.6248x over previous
#include <cuda_runtime.h>
#include <cuda_bf16.h>
#include <cstdint>

// Problem dims (fixed)
#define BB 2
#define SS 2048
#define DD 2048
#define HH 32
#define KVH 8
#define HD 64
#define MTOT (BB*SS)  // 4096

// ---------------- scratch ----------------
__device__ float g_q[(size_t)BB*SS*HH*HD];   // [b,s,h,d]  32MB
__device__ float g_k[(size_t)BB*SS*KVH*HD];  // 8MB
__device__ float g_v[(size_t)BB*SS*KVH*HD];  // 8MB
__device__ float g_o[(size_t)BB*SS*HH*HD];   // 32MB

__device__ __forceinline__ uint32_t f2tf32(float f) {
    uint32_t r; asm("cvt.rna.tf32.f32 %0, %1;" : "=r"(r) : "f"(f)); return r;
}

__device__ __forceinline__ void mma_tf32_16x8x8(
    float& d0, float& d1, float& d2, float& d3,
    uint32_t a0, uint32_t a1, uint32_t a2, uint32_t a3,
    uint32_t b0, uint32_t b1)
{
    asm volatile(
        "mma.sync.aligned.m16n8k8.row.col.f32.tf32.tf32.f32 "
        "{%0,%1,%2,%3}, {%4,%5,%6,%7}, {%8,%9}, {%0,%1,%2,%3};"
        : "+f"(d0), "+f"(d1), "+f"(d2), "+f"(d3)
        : "r"(a0), "r"(a1), "r"(a2), "r"(a3), "r"(b0), "r"(b1));
}

// ---------------- mma.sync tf32 GEMM: C[M,N] = A[M,K] @ B[N,K]^T ----------------
// CTA tile 128x128, 256 threads (4 m-warps x 2 n-warps), warp tile 32x64,
// K-chunk 32, smem [row][k] padded to 36 floats (conflict-free frag loads).
#define GBK 32
#define GPAD 36

__global__ __launch_bounds__(256) void gemm_mma(
    const float* __restrict__ A, const float* __restrict__ B,
    float* __restrict__ C, int M, int N, int K)
{
    __shared__ uint32_t As[128 * GPAD];
    __shared__ uint32_t Bs[128 * GPAD];

    const int tid  = threadIdx.x;
    const int warp = tid >> 5;
    const int lane = tid & 31;
    const int wm = (warp & 3) * 32;      // warp m-offset in tile
    const int wn = (warp >> 2) * 64;     // warp n-offset in tile
    const int m0 = blockIdx.y * 128;
    const int n0 = blockIdx.x * 128;

    // loader coords: each thread loads 1 row-half (16 floats = 4 float4) of A and B
    const int lrow = tid >> 1;           // 0..127
    const int lcol = (tid & 1) * 16;     // 0 or 16

    // fragment coords
    const int ar = lane >> 2;            // 0..7
    const int ac = lane & 3;             // 0..3

    float acc[2][8][4];
    #pragma unroll
    for (int i = 0; i < 2; i++)
        #pragma unroll
        for (int j = 0; j < 8; j++)
            #pragma unroll
            for (int l = 0; l < 4; l++) acc[i][j][l] = 0.0f;

    const float* Ap = A + (size_t)(m0 + lrow) * K + lcol;
    const float* Bp = B + (size_t)(n0 + lrow) * K + lcol;

    for (int k0 = 0; k0 < K; k0 += GBK) {
        // load + convert + store tiles
        #pragma unroll
        for (int i = 0; i < 4; i++) {
            float4 va = *(const float4*)(Ap + k0 + i * 4);
            float4 vb = *(const float4*)(Bp + k0 + i * 4);
            uint32_t* da = &As[lrow * GPAD + lcol + i * 4];
            uint32_t* db = &Bs[lrow * GPAD + lcol + i * 4];
            da[0] = f2tf32(va.x); da[1] = f2tf32(va.y);
            da[2] = f2tf32(va.z); da[3] = f2tf32(va.w);
            db[0] = f2tf32(vb.x); db[1] = f2tf32(vb.y);
            db[2] = f2tf32(vb.z); db[3] = f2tf32(vb.w);
        }
        __syncthreads();

        #pragma unroll
        for (int ks = 0; ks < 4; ks++) {
            const int kk = ks * 8;
            // A fragments: 2 m-frags of 16 rows
            uint32_t af[2][4];
            #pragma unroll
            for (int mi = 0; mi < 2; mi++) {
                const uint32_t* base = &As[(wm + mi * 16 + ar) * GPAD + kk + ac];
                af[mi][0] = base[0];
                af[mi][1] = base[8 * GPAD];
                af[mi][2] = base[4];
                af[mi][3] = base[8 * GPAD + 4];
            }
            // B fragments: 8 n-frags of 8 cols
            uint32_t bf[8][2];
            const int bc = lane >> 2;    // n within frag
            const int br = lane & 3;     // k within frag
            #pragma unroll
            for (int ni = 0; ni < 8; ni++) {
                const uint32_t* base = &Bs[(wn + ni * 8 + bc) * GPAD + kk + br];
                bf[ni][0] = base[0];
                bf[ni][1] = base[4];
            }
            #pragma unroll
            for (int mi = 0; mi < 2; mi++)
                #pragma unroll
                for (int ni = 0; ni < 8; ni++)
                    mma_tf32_16x8x8(acc[mi][ni][0], acc[mi][ni][1],
                                    acc[mi][ni][2], acc[mi][ni][3],
                                    af[mi][0], af[mi][1], af[mi][2], af[mi][3],
                                    bf[ni][0], bf[ni][1]);
        }
        __syncthreads();
    }

    // epilogue: write C (c0,c1 = row r, cols 2c..2c+1; c2,c3 = row r+8)
    const int cr = lane >> 2;
    const int cc = (lane & 3) * 2;
    #pragma unroll
    for (int mi = 0; mi < 2; mi++) {
        #pragma unroll
        for (int ni = 0; ni < 8; ni++) {
            size_t row = (size_t)(m0 + wm + mi * 16 + cr);
            int col = n0 + wn + ni * 8 + cc;
            *(float2*)&C[row * N + col] =
                make_float2(acc[mi][ni][0], acc[mi][ni][1]);
            *(float2*)&C[(row + 8) * N + col] =
                make_float2(acc[mi][ni][2], acc[mi][ni][3]);
        }
    }
}

// ---------------- RoPE (in-place, interleaved pairs) ----------------
__global__ void rope_kernel(float* __restrict__ buf,
                            const float* __restrict__ fc,
                            const float* __restrict__ fs,
                            int nh, int total)
{
    int idx = blockIdx.x * blockDim.x + threadIdx.x;
    if (idx >= total) return;
    int j = idx & 31;
    int t = idx >> 5;
    int s = (t / nh) % SS;
    float* p = buf + (size_t)t * HD + 2 * j;
    float2 v = *(float2*)p;
    float c = fc[s * 32 + j];
    float sn = fs[s * 32 + j];
    float2 r;
    r.x = v.x * c - v.y * sn;
    r.y = v.x * sn + v.y * c;
    *(float2*)p = r;
}

// ---------------- Flash attention (causal + pad mask), fp32 ----------------
#define NEG_BIG (-1e30f)

__global__ __launch_bounds__(256) void attn_kernel(
    const float* __restrict__ Qb, const float* __restrict__ Kb,
    const float* __restrict__ Vb, const int* __restrict__ amask,
    float* __restrict__ Ob)
{
    __shared__ float Qs[64][64];
    __shared__ float Ks[64][34];
    __shared__ float Vs[32][64];
    __shared__ float Ps[32][65];
    __shared__ float Ms[32];

    const int tid = threadIdx.x;
    const int tx = tid & 15;
    const int ty = tid >> 4;
    const int qb = blockIdx.x;
    const int h  = blockIdx.y;
    const int b  = blockIdx.z;
    const int q0 = qb * 64;
    const int kvh = h >> 2;
    const float scale = 0.125f;

    {
        int q  = tid >> 2;
        int dq = (tid & 3) * 4;
        const float* qp = Qb + (((size_t)b * SS + q0 + q) * HH + h) * HD;
        #pragma unroll
        for (int r = 0; r < 4; r++) {
            int d = dq + 16 * r;
            float4 v = *(const float4*)(qp + d);
            Qs[d + 0][q] = v.x * scale;
            Qs[d + 1][q] = v.y * scale;
            Qs[d + 2][q] = v.z * scale;
            Qs[d + 3][q] = v.w * scale;
        }
    }

    float m_i[4], l_i[4], o[4][4];
    #pragma unroll
    for (int i = 0; i < 4; i++) {
        m_i[i] = NEG_BIG;
        l_i[i] = 0.0f;
        #pragma unroll
        for (int j = 0; j < 4; j++) o[i][j] = 0.0f;
    }

    const int nkt = (q0 + 64) / 32;

    for (int kt = 0; kt < nkt; kt++) {
        const int k0 = kt * 32;
        {
            int k  = tid >> 3;
            int dq = (tid & 7) * 4;
            const float* kp = Kb + (((size_t)b * SS + k0 + k) * KVH + kvh) * HD;
            const float* vp = Vb + (((size_t)b * SS + k0 + k) * KVH + kvh) * HD;
            float4 v1 = *(const float4*)(kp + dq);
            float4 v2 = *(const float4*)(kp + dq + 32);
            Ks[dq + 0][k] = v1.x; Ks[dq + 1][k] = v1.y;
            Ks[dq + 2][k] = v1.z; Ks[dq + 3][k] = v1.w;
            Ks[dq + 32][k] = v2.x; Ks[dq + 33][k] = v2.y;
            Ks[dq + 34][k] = v2.z; Ks[dq + 35][k] = v2.w;
            float4 w1 = *(const float4*)(vp + dq);
            float4 w2 = *(const float4*)(vp + dq + 32);
            *(float4*)&Vs[k][dq]      = w1;
            *(float4*)&Vs[k][dq + 32] = w2;
        }
        if (tid < 32) Ms[tid] = amask[b * SS + k0 + tid] ? 0.0f : NEG_BIG;
        __syncthreads();

        float s[4][2];
        #pragma unroll
        for (int i = 0; i < 4; i++) { s[i][0] = 0.0f; s[i][1] = 0.0f; }
        #pragma unroll 16
        for (int d = 0; d < 64; d++) {
            float4 a = *(const float4*)&Qs[d][ty * 4];
            float2 bv = *(const float2*)&Ks[d][tx * 2];
            s[0][0] += a.x * bv.x; s[0][1] += a.x * bv.y;
            s[1][0] += a.y * bv.x; s[1][1] += a.y * bv.y;
            s[2][0] += a.z * bv.x; s[2][1] += a.z * bv.y;
            s[3][0] += a.w * bv.x; s[3][1] += a.w * bv.y;
        }

        float msk0 = Ms[tx * 2 + 0];
        float msk1 = Ms[tx * 2 + 1];
        #pragma unroll
        for (int i = 0; i < 4; i++) {
            int qg = q0 + ty * 4 + i;
            float sv0 = s[i][0] + msk0;
            float sv1 = s[i][1] + msk1;
            if (k0 + tx * 2 + 0 > qg) sv0 = NEG_BIG;
            if (k0 + tx * 2 + 1 > qg) sv1 = NEG_BIG;
            float rmax = fmaxf(sv0, sv1);
            #pragma unroll
            for (int off = 8; off > 0; off >>= 1)
                rmax = fmaxf(rmax, __shfl_xor_sync(0xffffffffu, rmax, off));
            float mnew = fmaxf(m_i[i], rmax);
            float corr = __expf(m_i[i] - mnew);
            m_i[i] = mnew;
            float p0 = __expf(sv0 - mnew);
            float p1 = __expf(sv1 - mnew);
            float rsum = p0 + p1;
            #pragma unroll
            for (int off = 8; off > 0; off >>= 1)
                rsum += __shfl_xor_sync(0xffffffffu, rsum, off);
            l_i[i] = l_i[i] * corr + rsum;
            o[i][0] *= corr; o[i][1] *= corr; o[i][2] *= corr; o[i][3] *= corr;
            Ps[tx * 2 + 0][ty * 4 + i] = p0;
            Ps[tx * 2 + 1][ty * 4 + i] = p1;
        }
        __syncthreads();

        #pragma unroll 8
        for (int k = 0; k < 32; k++) {
            float a0 = Ps[k][ty * 4 + 0];
            float a1 = Ps[k][ty * 4 + 1];
            float a2 = Ps[k][ty * 4 + 2];
            float a3 = Ps[k][ty * 4 + 3];
            float4 bv = *(const float4*)&Vs[k][tx * 4];
            o[0][0] += a0 * bv.x; o[0][1] += a0 * bv.y; o[0][2] += a0 * bv.z; o[0][3] += a0 * bv.w;
            o[1][0] += a1 * bv.x; o[1][1] += a1 * bv.y; o[1][2] += a1 * bv.z; o[1][3] += a1 * bv.w;
            o[2][0] += a2 * bv.x; o[2][1] += a2 * bv.y; o[2][2] += a2 * bv.z; o[2][3] += a2 * bv.w;
            o[3][0] += a3 * bv.x; o[3][1] += a3 * bv.y; o[3][2] += a3 * bv.z; o[3][3] += a3 * bv.w;
        }
        __syncthreads();
    }

    #pragma unroll
    for (int i = 0; i < 4; i++) {
        float inv = 1.0f / l_i[i];
        int q = q0 + ty * 4 + i;
        float4 v = make_float4(o[i][0] * inv, o[i][1] * inv, o[i][2] * inv, o[i][3] * inv);
        *(float4*)&Ob[(((size_t)b * SS + q) * HH + h) * HD + tx * 4] = v;
    }
}

// ---------------- launch ----------------
extern "C" void kernel_launch(void* const* d_in, const int* in_sizes, int n_in,
                              void* d_out, int out_size)
{
    const float* x  = (const float*)d_in[0];
    const float* fc = (const float*)d_in[1];
    const float* fs = (const float*)d_in[2];
    const float* wq = (const float*)d_in[3];
    const float* wk = (const float*)d_in[4];
    const float* wv = (const float*)d_in[5];
    const float* wo = (const float*)d_in[6];
    const int*   am = (const int*)d_in[7];
    float* out = (float*)d_out;

    float *pq, *pk, *pv, *po;
    cudaGetSymbolAddress((void**)&pq, g_q);
    cudaGetSymbolAddress((void**)&pk, g_k);
    cudaGetSymbolAddress((void**)&pv, g_v);
    cudaGetSymbolAddress((void**)&po, g_o);

    // QKV projections on tensor cores (tf32 mma.sync)
    gemm_mma<<<dim3(DD / 128, MTOT / 128), 256>>>(x, wq, pq, MTOT, DD, DD);
    gemm_mma<<<dim3((KVH * HD) / 128, MTOT / 128), 256>>>(x, wk, pk, MTOT, KVH * HD, DD);
    gemm_mma<<<dim3((KVH * HD) / 128, MTOT / 128), 256>>>(x, wv, pv, MTOT, KVH * HD, DD);

    // RoPE on Q and K
    {
        int totq = BB * SS * HH * 32;
        int totk = BB * SS * KVH * 32;
        rope_kernel<<<(totq + 255) / 256, 256>>>(pq, fc, fs, HH, totq);
        rope_kernel<<<(totk + 255) / 256, 256>>>(pk, fc, fs, KVH, totk);
    }

    // attention (fp32 CUDA cores, flash-style)
    attn_kernel<<<dim3(SS / 64, HH, BB), 256>>>(pq, pk, pv, am, po);

    // output projection on tensor cores
    gemm_mma<<<dim3(DD / 128, MTOT / 128), 256>>>(po, wo, out, MTOT, DD, DD);
}

// round 13
// speedup vs baseline: 2.3282x; 1.4329x over previous
#include <cuda_runtime.h>
#include <cuda_bf16.h>
#include <cstdint>

// Problem dims (fixed)
#define BB 2
#define SS 2048
#define DD 2048
#define HH 32
#define KVH 8
#define HD 64
#define MTOT (BB*SS)  // 4096

// ---------------- scratch ----------------
__device__ float g_q[(size_t)BB*SS*HH*HD];   // [b,s,h,d]  32MB
__device__ float g_k[(size_t)BB*SS*KVH*HD];  // 8MB
__device__ float g_v[(size_t)BB*SS*KVH*HD];  // 8MB
__device__ float g_o[(size_t)BB*SS*HH*HD];   // 32MB

__device__ __forceinline__ uint32_t f2tf32(float f) {
    uint32_t r; asm("cvt.rna.tf32.f32 %0, %1;" : "=r"(r) : "f"(f)); return r;
}

__device__ __forceinline__ void mma_tf32_16x8x8(
    float& d0, float& d1, float& d2, float& d3,
    uint32_t a0, uint32_t a1, uint32_t a2, uint32_t a3,
    uint32_t b0, uint32_t b1)
{
    asm volatile(
        "mma.sync.aligned.m16n8k8.row.col.f32.tf32.tf32.f32 "
        "{%0,%1,%2,%3}, {%4,%5,%6,%7}, {%8,%9}, {%0,%1,%2,%3};"
        : "+f"(d0), "+f"(d1), "+f"(d2), "+f"(d3)
        : "r"(a0), "r"(a1), "r"(a2), "r"(a3), "r"(b0), "r"(b1));
}

// ---------------- mma.sync tf32 GEMM: C[M,N] = A[M,K] @ B[N,K]^T ----------------
#define GBK 32
#define GPAD 36

__global__ __launch_bounds__(256) void gemm_mma(
    const float* __restrict__ A, const float* __restrict__ B,
    float* __restrict__ C, int M, int N, int K)
{
    __shared__ uint32_t As[128 * GPAD];
    __shared__ uint32_t Bs[128 * GPAD];

    const int tid  = threadIdx.x;
    const int warp = tid >> 5;
    const int lane = tid & 31;
    const int wm = (warp & 3) * 32;
    const int wn = (warp >> 2) * 64;
    const int m0 = blockIdx.y * 128;
    const int n0 = blockIdx.x * 128;

    const int lrow = tid >> 1;
    const int lcol = (tid & 1) * 16;

    const int ar = lane >> 2;
    const int ac = lane & 3;

    float acc[2][8][4];
    #pragma unroll
    for (int i = 0; i < 2; i++)
        #pragma unroll
        for (int j = 0; j < 8; j++)
            #pragma unroll
            for (int l = 0; l < 4; l++) acc[i][j][l] = 0.0f;

    const float* Ap = A + (size_t)(m0 + lrow) * K + lcol;
    const float* Bp = B + (size_t)(n0 + lrow) * K + lcol;

    for (int k0 = 0; k0 < K; k0 += GBK) {
        #pragma unroll
        for (int i = 0; i < 4; i++) {
            float4 va = *(const float4*)(Ap + k0 + i * 4);
            float4 vb = *(const float4*)(Bp + k0 + i * 4);
            uint32_t* da = &As[lrow * GPAD + lcol + i * 4];
            uint32_t* db = &Bs[lrow * GPAD + lcol + i * 4];
            da[0] = f2tf32(va.x); da[1] = f2tf32(va.y);
            da[2] = f2tf32(va.z); da[3] = f2tf32(va.w);
            db[0] = f2tf32(vb.x); db[1] = f2tf32(vb.y);
            db[2] = f2tf32(vb.z); db[3] = f2tf32(vb.w);
        }
        __syncthreads();

        #pragma unroll
        for (int ks = 0; ks < 4; ks++) {
            const int kk = ks * 8;
            uint32_t af[2][4];
            #pragma unroll
            for (int mi = 0; mi < 2; mi++) {
                const uint32_t* base = &As[(wm + mi * 16 + ar) * GPAD + kk + ac];
                af[mi][0] = base[0];
                af[mi][1] = base[8 * GPAD];
                af[mi][2] = base[4];
                af[mi][3] = base[8 * GPAD + 4];
            }
            uint32_t bf[8][2];
            #pragma unroll
            for (int ni = 0; ni < 8; ni++) {
                const uint32_t* base = &Bs[(wn + ni * 8 + ar) * GPAD + kk + ac];
                bf[ni][0] = base[0];
                bf[ni][1] = base[4];
            }
            #pragma unroll
            for (int mi = 0; mi < 2; mi++)
                #pragma unroll
                for (int ni = 0; ni < 8; ni++)
                    mma_tf32_16x8x8(acc[mi][ni][0], acc[mi][ni][1],
                                    acc[mi][ni][2], acc[mi][ni][3],
                                    af[mi][0], af[mi][1], af[mi][2], af[mi][3],
                                    bf[ni][0], bf[ni][1]);
        }
        __syncthreads();
    }

    const int cr = lane >> 2;
    const int cc = (lane & 3) * 2;
    #pragma unroll
    for (int mi = 0; mi < 2; mi++) {
        #pragma unroll
        for (int ni = 0; ni < 8; ni++) {
            size_t row = (size_t)(m0 + wm + mi * 16 + cr);
            int col = n0 + wn + ni * 8 + cc;
            *(float2*)&C[row * N + col] =
                make_float2(acc[mi][ni][0], acc[mi][ni][1]);
            *(float2*)&C[(row + 8) * N + col] =
                make_float2(acc[mi][ni][2], acc[mi][ni][3]);
        }
    }
}

// ---------------- RoPE (in-place, interleaved pairs) ----------------
__global__ void rope_kernel(float* __restrict__ buf,
                            const float* __restrict__ fc,
                            const float* __restrict__ fs,
                            int nh, int total)
{
    int idx = blockIdx.x * blockDim.x + threadIdx.x;
    if (idx >= total) return;
    int j = idx & 31;
    int t = idx >> 5;
    int s = (t / nh) % SS;
    float* p = buf + (size_t)t * HD + 2 * j;
    float2 v = *(float2*)p;
    float c = fc[s * 32 + j];
    float sn = fs[s * 32 + j];
    float2 r;
    r.x = v.x * c - v.y * sn;
    r.y = v.x * sn + v.y * c;
    *(float2*)p = r;
}

// ---------------- Flash attention on mma.sync tf32 ----------------
// BQ=64 per CTA, BK=32 per tile, 128 threads (4 warps x 16 q-rows each).
// fp32 online softmax; QK^T and P.V on tensor cores.
#define NEG_BIG (-1e30f)
#define QPAD 68
#define VPAD 36

__global__ __launch_bounds__(128) void attn_mma(
    const float* __restrict__ Qb, const float* __restrict__ Kb,
    const float* __restrict__ Vb, const int* __restrict__ amask,
    float* __restrict__ Ob)
{
    __shared__ uint32_t Qs[64][QPAD];   // [q][d] tf32, scaled
    __shared__ uint32_t Ks[32][QPAD];   // [key][d] tf32
    __shared__ uint32_t Vs[64][VPAD];   // [d][key] tf32 (transposed)
    __shared__ uint32_t Ps[64][VPAD];   // [q][key] tf32
    __shared__ float Ms[32];            // pad mask per key

    const int tid  = threadIdx.x;
    const int warp = tid >> 5;
    const int lane = tid & 31;
    const int ar = lane >> 2;       // 0..7
    const int ac = lane & 3;        // 0..3
    const int wq = warp * 16;

    const int q0 = blockIdx.x * 64;
    const int h  = blockIdx.y;
    const int b  = blockIdx.z;
    const int kvh = h >> 2;
    const float scale = 0.125f;

    // load Q (scaled, tf32)
    {
        int row = tid >> 1;
        int c0  = (tid & 1) * 32;
        const float* qp = Qb + (((size_t)b * SS + q0 + row) * HH + h) * HD + c0;
        #pragma unroll
        for (int i = 0; i < 8; i++) {
            float4 v = *(const float4*)(qp + i * 4);
            uint32_t* d = &Qs[row][c0 + i * 4];
            d[0] = f2tf32(v.x * scale); d[1] = f2tf32(v.y * scale);
            d[2] = f2tf32(v.z * scale); d[3] = f2tf32(v.w * scale);
        }
    }

    float m_lo = NEG_BIG, m_hi = NEG_BIG, l_lo = 0.0f, l_hi = 0.0f;
    float o[8][4];
    #pragma unroll
    for (int i = 0; i < 8; i++)
        #pragma unroll
        for (int j = 0; j < 4; j++) o[i][j] = 0.0f;

    const int nkt = (q0 + 64) / 32;

    for (int kt = 0; kt < nkt; kt++) {
        const int k0 = kt * 32;
        // load K [key][d] and V transposed [d][key]
        {
            int row = tid >> 2;           // 0..31
            int c0  = (tid & 3) * 16;
            const float* kp = Kb + (((size_t)b * SS + k0 + row) * KVH + kvh) * HD + c0;
            const float* vp = Vb + (((size_t)b * SS + k0 + row) * KVH + kvh) * HD + c0;
            #pragma unroll
            for (int i = 0; i < 4; i++) {
                float4 v = *(const float4*)(kp + i * 4);
                uint32_t* d = &Ks[row][c0 + i * 4];
                d[0] = f2tf32(v.x); d[1] = f2tf32(v.y);
                d[2] = f2tf32(v.z); d[3] = f2tf32(v.w);
                float4 w = *(const float4*)(vp + i * 4);
                Vs[c0 + i * 4 + 0][row] = f2tf32(w.x);
                Vs[c0 + i * 4 + 1][row] = f2tf32(w.y);
                Vs[c0 + i * 4 + 2][row] = f2tf32(w.z);
                Vs[c0 + i * 4 + 3][row] = f2tf32(w.w);
            }
        }
        if (tid < 32) Ms[tid] = amask[b * SS + k0 + tid] ? 0.0f : NEG_BIG;
        __syncthreads();

        // S = Q K^T
        float s[4][4];
        #pragma unroll
        for (int i = 0; i < 4; i++)
            #pragma unroll
            for (int j = 0; j < 4; j++) s[i][j] = 0.0f;

        #pragma unroll
        for (int ks = 0; ks < 8; ks++) {
            const int kk = ks * 8;
            uint32_t a0 = Qs[wq + ar][kk + ac];
            uint32_t a1 = Qs[wq + ar + 8][kk + ac];
            uint32_t a2 = Qs[wq + ar][kk + ac + 4];
            uint32_t a3 = Qs[wq + ar + 8][kk + ac + 4];
            #pragma unroll
            for (int ni = 0; ni < 4; ni++) {
                uint32_t b0 = Ks[ni * 8 + ar][kk + ac];
                uint32_t b1 = Ks[ni * 8 + ar][kk + ac + 4];
                mma_tf32_16x8x8(s[ni][0], s[ni][1], s[ni][2], s[ni][3],
                                a0, a1, a2, a3, b0, b1);
            }
        }

        // mask + online softmax (rows ar and ar+8 of this warp's 16)
        const int rg_lo = q0 + wq + ar;
        const int rg_hi = rg_lo + 8;
        float rmax_lo = NEG_BIG, rmax_hi = NEG_BIG;
        #pragma unroll
        for (int ni = 0; ni < 4; ni++) {
            int cl = ni * 8 + 2 * ac;
            int cg = k0 + cl;
            float mk0 = Ms[cl], mk1 = Ms[cl + 1];
            s[ni][0] += mk0; if (cg     > rg_lo) s[ni][0] = NEG_BIG;
            s[ni][1] += mk1; if (cg + 1 > rg_lo) s[ni][1] = NEG_BIG;
            s[ni][2] += mk0; if (cg     > rg_hi) s[ni][2] = NEG_BIG;
            s[ni][3] += mk1; if (cg + 1 > rg_hi) s[ni][3] = NEG_BIG;
            rmax_lo = fmaxf(rmax_lo, fmaxf(s[ni][0], s[ni][1]));
            rmax_hi = fmaxf(rmax_hi, fmaxf(s[ni][2], s[ni][3]));
        }
        rmax_lo = fmaxf(rmax_lo, __shfl_xor_sync(0xffffffffu, rmax_lo, 1));
        rmax_lo = fmaxf(rmax_lo, __shfl_xor_sync(0xffffffffu, rmax_lo, 2));
        rmax_hi = fmaxf(rmax_hi, __shfl_xor_sync(0xffffffffu, rmax_hi, 1));
        rmax_hi = fmaxf(rmax_hi, __shfl_xor_sync(0xffffffffu, rmax_hi, 2));

        float mn_lo = fmaxf(m_lo, rmax_lo);
        float mn_hi = fmaxf(m_hi, rmax_hi);
        float corr_lo = __expf(m_lo - mn_lo);
        float corr_hi = __expf(m_hi - mn_hi);
        m_lo = mn_lo; m_hi = mn_hi;

        float rsum_lo = 0.0f, rsum_hi = 0.0f;
        #pragma unroll
        for (int ni = 0; ni < 4; ni++) {
            int cl = ni * 8 + 2 * ac;
            float p0 = __expf(s[ni][0] - mn_lo);
            float p1 = __expf(s[ni][1] - mn_lo);
            float p2 = __expf(s[ni][2] - mn_hi);
            float p3 = __expf(s[ni][3] - mn_hi);
            rsum_lo += p0 + p1;
            rsum_hi += p2 + p3;
            Ps[wq + ar][cl]         = f2tf32(p0);
            Ps[wq + ar][cl + 1]     = f2tf32(p1);
            Ps[wq + ar + 8][cl]     = f2tf32(p2);
            Ps[wq + ar + 8][cl + 1] = f2tf32(p3);
        }
        rsum_lo += __shfl_xor_sync(0xffffffffu, rsum_lo, 1);
        rsum_lo += __shfl_xor_sync(0xffffffffu, rsum_lo, 2);
        rsum_hi += __shfl_xor_sync(0xffffffffu, rsum_hi, 1);
        rsum_hi += __shfl_xor_sync(0xffffffffu, rsum_hi, 2);
        l_lo = l_lo * corr_lo + rsum_lo;
        l_hi = l_hi * corr_hi + rsum_hi;

        #pragma unroll
        for (int ni = 0; ni < 8; ni++) {
            o[ni][0] *= corr_lo; o[ni][1] *= corr_lo;
            o[ni][2] *= corr_hi; o[ni][3] *= corr_hi;
        }
        __syncwarp();

        // O += P @ V
        #pragma unroll
        for (int ks = 0; ks < 4; ks++) {
            const int kk = ks * 8;
            uint32_t a0 = Ps[wq + ar][kk + ac];
            uint32_t a1 = Ps[wq + ar + 8][kk + ac];
            uint32_t a2 = Ps[wq + ar][kk + ac + 4];
            uint32_t a3 = Ps[wq + ar + 8][kk + ac + 4];
            #pragma unroll
            for (int ni = 0; ni < 8; ni++) {
                uint32_t b0 = Vs[ni * 8 + ar][kk + ac];
                uint32_t b1 = Vs[ni * 8 + ar][kk + ac + 4];
                mma_tf32_16x8x8(o[ni][0], o[ni][1], o[ni][2], o[ni][3],
                                a0, a1, a2, a3, b0, b1);
            }
        }
        __syncthreads();
    }

    // epilogue
    const float inv_lo = 1.0f / l_lo;
    const float inv_hi = 1.0f / l_hi;
    const int row_lo = q0 + wq + ar;
    #pragma unroll
    for (int ni = 0; ni < 8; ni++) {
        int d = ni * 8 + 2 * ac;
        *(float2*)&Ob[(((size_t)b * SS + row_lo) * HH + h) * HD + d] =
            make_float2(o[ni][0] * inv_lo, o[ni][1] * inv_lo);
        *(float2*)&Ob[(((size_t)b * SS + row_lo + 8) * HH + h) * HD + d] =
            make_float2(o[ni][2] * inv_hi, o[ni][3] * inv_hi);
    }
}

// ---------------- launch ----------------
extern "C" void kernel_launch(void* const* d_in, const int* in_sizes, int n_in,
                              void* d_out, int out_size)
{
    const float* x  = (const float*)d_in[0];
    const float* fc = (const float*)d_in[1];
    const float* fs = (const float*)d_in[2];
    const float* wq = (const float*)d_in[3];
    const float* wk = (const float*)d_in[4];
    const float* wv = (const float*)d_in[5];
    const float* wo = (const float*)d_in[6];
    const int*   am = (const int*)d_in[7];
    float* out = (float*)d_out;

    float *pq, *pk, *pv, *po;
    cudaGetSymbolAddress((void**)&pq, g_q);
    cudaGetSymbolAddress((void**)&pk, g_k);
    cudaGetSymbolAddress((void**)&pv, g_v);
    cudaGetSymbolAddress((void**)&po, g_o);

    // QKV projections on tensor cores (tf32 mma.sync)
    gemm_mma<<<dim3(DD / 128, MTOT / 128), 256>>>(x, wq, pq, MTOT, DD, DD);
    gemm_mma<<<dim3((KVH * HD) / 128, MTOT / 128), 256>>>(x, wk, pk, MTOT, KVH * HD, DD);
    gemm_mma<<<dim3((KVH * HD) / 128, MTOT / 128), 256>>>(x, wv, pv, MTOT, KVH * HD, DD);

    // RoPE on Q and K
    {
        int totq = BB * SS * HH * 32;
        int totk = BB * SS * KVH * 32;
        rope_kernel<<<(totq + 255) / 256, 256>>>(pq, fc, fs, HH, totq);
        rope_kernel<<<(totk + 255) / 256, 256>>>(pk, fc, fs, KVH, totk);
    }

    // attention on tensor cores (tf32 mma.sync flash)
    attn_mma<<<dim3(SS / 64, HH, BB), 128>>>(pq, pk, pv, am, po);

    // output projection on tensor cores
    gemm_mma<<<dim3(DD / 128, MTOT / 128), 256>>>(po, wo, out, MTOT, DD, DD);
}